// round 3
// baseline (speedup 1.0000x reference)
#include <cuda_runtime.h>
#include <math.h>
#include <stdint.h>

#define BB 16
#define AA 65472
#define CC 81
#define GG 50

__device__ float  g_best_iou[BB * AA];
__device__ int    g_best_idx[BB * AA];
__device__ int    g_labels[BB * AA];
__device__ float  g_mining[BB * AA];
__device__ unsigned long long g_gt_pack[BB * GG];
__device__ int    g_num_pos[BB];
__device__ double g_loc_sum;
__device__ double g_ce_sum;
__device__ double g_topk_sum[BB];
__device__ unsigned int g_hist[BB][256];

__device__ __forceinline__ unsigned int okey(float f) {
    unsigned int u = __float_as_uint(f);
    return (u & 0x80000000u) ? ~u : (u | 0x80000000u);
}

__global__ void k_init() {
    int i = blockIdx.x * blockDim.x + threadIdx.x;
    if (i < BB * GG) g_gt_pack[i] = 0xFFFFFFFFull;  // iou=0, anchor=0 default
    if (i < BB) { g_num_pos[i] = 0; g_topk_sum[i] = 0.0; }
    if (i == 0) { g_loc_sum = 0.0; g_ce_sum = 0.0; }
    if (i < BB * 256) ((unsigned int*)g_hist)[i] = 0u;
}

__global__ void __launch_bounds__(256) k_match(const float* __restrict__ gts,
                                               const int* __restrict__ counts,
                                               const float* __restrict__ anchors) {
    int b = blockIdx.y;
    int a = blockIdx.x * 256 + threadIdx.x;
    __shared__ float4 sbox[GG];
    __shared__ float  sarea[GG];
    __shared__ unsigned long long spack[GG];
    int t = threadIdx.x;
    if (t < GG) {
        const float* gp = gts + ((size_t)b * GG + t) * 5;
        float4 bx = make_float4(gp[0], gp[1], gp[2], gp[3]);
        sbox[t] = bx;
        sarea[t] = (bx.z - bx.x) * (bx.w - bx.y) + 1e-10f;
        spack[t] = 0ull;
    }
    __syncthreads();
    int count = counts[b];
    if (a < AA) {
        float4 an = ((const float4*)anchors)[a];
        float areaA = (an.z - an.x) * (an.w - an.y);
        float best_q = 0.0f;
        int   best_g = 0;
        unsigned int inva = 0xFFFFFFFFu - (unsigned int)a;
#pragma unroll 4
        for (int g = 0; g < count; g++) {
            float4 bx = sbox[g];
            float wx = fminf(an.z, bx.z) - fmaxf(an.x, bx.x);
            float wy = fminf(an.w, bx.w) - fmaxf(an.y, bx.y);
            wx = fmaxf(wx, 0.0f); wy = fmaxf(wy, 0.0f);
            float inter = wx * wy;
            float q = __fdividef(inter, areaA + sarea[g] - inter);
            if (q > best_q) { best_q = q; best_g = g; }       // first-max (asc g)
            if (inter > 0.0f) {
                unsigned long long pk =
                    (((unsigned long long)__float_as_uint(q)) << 32) | inva;
                if (pk > spack[g]) atomicMax(&spack[g], pk);  // racy read = filter
            }
        }
        size_t idx = (size_t)b * AA + a;
        g_best_iou[idx] = best_q;
        g_best_idx[idx] = best_g;
    }
    __syncthreads();
    if (t < count && spack[t]) atomicMax(&g_gt_pack[b * GG + t], spack[t]);
}

__global__ void k_force(const int* __restrict__ counts) {
    int b = blockIdx.x;
    int j = threadIdx.x;
    __shared__ unsigned int sa[GG];
    int count = counts[b];
    unsigned int a = 0;
    if (j < count) {
        unsigned long long pk = g_gt_pack[b * GG + j];
        a = 0xFFFFFFFFu - (unsigned int)(pk & 0xFFFFFFFFull);
        sa[j] = a;
    }
    __syncthreads();
    if (j < count) {
        bool ok = true;                    // duplicate scatter: last j wins
        for (int j2 = j + 1; j2 < count; j2++)
            if (sa[j2] == a) ok = false;
        if (ok) {
            g_best_iou[(size_t)b * AA + a] = 2.0f;
            g_best_idx[(size_t)b * AA + a] = j;
        }
    }
}

__global__ void __launch_bounds__(256) k_loc(const float* __restrict__ gts,
                                             const float* __restrict__ anchors,
                                             const float* __restrict__ pred) {
    int b = blockIdx.y;
    int a = blockIdx.x * 256 + threadIdx.x;
    __shared__ double s_loc;
    __shared__ int s_np;
    if (threadIdx.x == 0) { s_loc = 0.0; s_np = 0; }
    __syncthreads();
    float lsum = 0.0f;
    int ispos = 0;
    if (a < AA) {
        size_t idx = (size_t)b * AA + a;
        float q = g_best_iou[idx];
        int g = g_best_idx[idx];
        int label = 0;
        if (q >= 0.5f) {
            const float* gp = gts + ((size_t)b * GG + g) * 5;
            label = (int)gp[4];
            ispos = 1;
            float4 an = ((const float4*)anchors)[a];
            float acx = (an.x + an.z) * 0.5f, acy = (an.y + an.w) * 0.5f;
            float aw = an.z - an.x, ah = an.w - an.y;
            float mcx = (gp[0] + gp[2]) * 0.5f, mcy = (gp[1] + gp[3]) * 0.5f;
            float mw = gp[2] - gp[0], mh = gp[3] - gp[1];
            float t0 = (mcx - acx) / (aw * 0.1f);
            float t1 = (mcy - acy) / (ah * 0.1f);
            float t2 = logf(mw / aw + 1e-10f) * 5.0f;
            float t3 = logf(mh / ah + 1e-10f) * 5.0f;
            float4 p = ((const float4*)pred)[idx];
            float n0 = fabsf(p.x - t0), n1 = fabsf(p.y - t1);
            float n2 = fabsf(p.z - t2), n3 = fabsf(p.w - t3);
            const float BETA = 1.0f / 9.0f;
            lsum = (n0 < BETA ? 4.5f * n0 * n0 : n0 - 0.5f * BETA)
                 + (n1 < BETA ? 4.5f * n1 * n1 : n1 - 0.5f * BETA)
                 + (n2 < BETA ? 4.5f * n2 * n2 : n2 - 0.5f * BETA)
                 + (n3 < BETA ? 4.5f * n3 * n3 : n3 - 0.5f * BETA);
        }
        g_labels[idx] = label;
    }
    for (int o = 16; o; o >>= 1) {
        lsum  += __shfl_down_sync(0xffffffffu, lsum, o);
        ispos += __shfl_down_sync(0xffffffffu, ispos, o);
    }
    if ((threadIdx.x & 31) == 0 && ispos) {
        atomicAdd(&s_np, ispos);
        atomicAdd(&s_loc, (double)lsum);
    }
    __syncthreads();
    if (threadIdx.x == 0 && s_np) {
        atomicAdd(&g_num_pos[b], s_np);
        atomicAdd(&g_loc_sum, s_loc);
    }
}

// warp per anchor row: log-softmax + mining value + positive CE
__global__ void __launch_bounds__(256) k_conf(const float* __restrict__ conf) {
    int wg = (blockIdx.x * 256 + threadIdx.x) >> 5;
    int lane = threadIdx.x & 31;
    if (wg >= BB * AA) return;
    size_t base = (size_t)wg * CC;
    float v0 = conf[base + lane];
    float v1 = conf[base + 32 + lane];
    float v2 = (lane < CC - 64) ? conf[base + 64 + lane] : 0.0f;
    int label = g_labels[wg];
    float e = __expf(v0) + __expf(v1) + ((lane < CC - 64) ? __expf(v2) : 0.0f);
    float sel = 0.0f;
    if (label > 0) {
        if (label < 32)      { if (lane == label)      sel = v0; }
        else if (label < 64) { if (lane == label - 32) sel = v1; }
        else                 { if (lane == label - 64) sel = v2; }
    }
    for (int o = 16; o; o >>= 1) {
        e   += __shfl_xor_sync(0xffffffffu, e, o);
        sel += __shfl_xor_sync(0xffffffffu, sel, o);
    }
    float lse = __logf(e);
    float c0 = __shfl_sync(0xffffffffu, v0, 0);
    if (lane == 0) {
        g_mining[wg] = (label > 0) ? __int_as_float(0xff800000) : (lse - c0);
        if (label > 0) atomicAdd(&g_ce_sum, (double)(lse - sel));
    }
}

__global__ void __launch_bounds__(256) k_hist() {
    int b = blockIdx.y;
    __shared__ unsigned int h[256];
    h[threadIdx.x] = 0;
    __syncthreads();
    const int chunk = AA / 32;                       // 2046 exact
    size_t base = (size_t)b * AA + (size_t)blockIdx.x * chunk;
    for (int i = threadIdx.x; i < chunk; i += 256)
        atomicAdd(&h[okey(g_mining[base + i]) >> 24], 1u);
    __syncthreads();
    if (h[threadIdx.x]) atomicAdd(&g_hist[b][threadIdx.x], h[threadIdx.x]);
}

__global__ void __launch_bounds__(256) k_select() {
    int b = blockIdx.x;
    __shared__ unsigned int h[256];
    __shared__ unsigned int s_prefix;
    __shared__ int s_r;
    __shared__ double sd[256];
    int np = g_num_pos[b];
    long long kk = 3LL * np;
    int neg = AA - np;
    int k = (kk < (long long)neg) ? (int)kk : neg;

    if (threadIdx.x == 0) {
        int r = k, cum = 0;
        unsigned int pfx = 0;
        for (int bin = 255; bin >= 0; bin--) {
            int c = (int)g_hist[b][bin];
            if (cum + c >= r) { pfx = (unsigned int)bin << 24; r -= cum; break; }
            cum += c;
        }
        s_prefix = pfx; s_r = r;
    }
    __syncthreads();

    for (int byte = 2; byte >= 0; byte--) {
        h[threadIdx.x] = 0;
        __syncthreads();
        unsigned int pfx = s_prefix;
        int sh = 8 * (byte + 1);
        for (int i = threadIdx.x; i < AA; i += 256) {
            unsigned int key = okey(g_mining[(size_t)b * AA + i]);
            if ((key >> sh) == (pfx >> sh))
                atomicAdd(&h[(key >> (8 * byte)) & 255u], 1u);
        }
        __syncthreads();
        if (threadIdx.x == 0) {
            int r = s_r, cum = 0;
            unsigned int pfx2 = s_prefix;
            for (int bin = 255; bin >= 0; bin--) {
                int c = (int)h[bin];
                if (cum + c >= r) { pfx2 |= (unsigned int)bin << (8 * byte); r -= cum; break; }
                cum += c;
            }
            s_prefix = pfx2; s_r = r;
        }
        __syncthreads();
    }

    unsigned int T = s_prefix;
    double ds = 0.0;
    for (int i = threadIdx.x; i < AA; i += 256) {
        float v = g_mining[(size_t)b * AA + i];
        if (okey(v) > T) ds += (double)v;
    }
    sd[threadIdx.x] = ds;
    __syncthreads();
    for (int o = 128; o; o >>= 1) {
        if (threadIdx.x < o) sd[threadIdx.x] += sd[threadIdx.x + o];
        __syncthreads();
    }
    if (threadIdx.x == 0) {
        unsigned int bits = (T & 0x80000000u) ? (T ^ 0x80000000u) : ~T;
        float vT = __uint_as_float(bits);
        g_topk_sum[b] = sd[0] + (double)s_r * (double)vT;
    }
}

__global__ void k_final(float* __restrict__ out) {
    long long np = 0;
    double tk = 0.0;
    for (int b = 0; b < BB; b++) { np += g_num_pos[b]; tk += g_topk_sum[b]; }
    double num_pos = (np < 1) ? 1.0 : (double)np;
    double inv = 1.0 / (num_pos * 4.0);
    out[0] = (float)(g_loc_sum * inv);
    out[1] = (float)((g_ce_sum + tk) * inv);
}

extern "C" void kernel_launch(void* const* d_in, const int* in_sizes, int n_in,
                              void* d_out, int out_size) {
    const float* conf    = (const float*)d_in[0];
    const float* pred    = (const float*)d_in[1];
    const float* gts     = (const float*)d_in[2];
    const int*   counts  = (const int*)  d_in[3];
    const float* anchors = (const float*)d_in[4];
    float* out = (float*)d_out;

    k_init<<<16, 256>>>();
    dim3 gm((AA + 255) / 256, BB);
    k_match<<<gm, 256>>>(gts, counts, anchors);
    k_force<<<BB, GG>>>(counts);
    k_loc<<<gm, 256>>>(gts, anchors, pred);
    k_conf<<<(BB * AA) / 8, 256>>>(conf);
    k_hist<<<dim3(32, BB), 256>>>();
    k_select<<<BB, 256>>>();
    k_final<<<1, 1>>>(out);
}